// round 1
// baseline (speedup 1.0000x reference)
#include <cuda_runtime.h>
#include <cuda_bf16.h>
#include <cstdint>
#include <cstddef>

// ---------------------------------------------------------------------------
// Problem dims
// ---------------------------------------------------------------------------
#define B_    512
#define SIG_  512
#define HID_  1024
#define EDGE_ 512
#define SLOTS_ 256
#define MEM_  512
#define IOC_  256
#define GRP_  32
#define CATK_ (EDGE_ + GRP_)   // 544

// Output layout (floats), tuple order: latent, refined, energy, io, new_memory, weights
#define OUT_LATENT   0u
#define OUT_REFINED  (OUT_LATENT  + (size_t)B_*HID_)        // 524288
#define OUT_ENERGY   (OUT_REFINED + (size_t)B_*EDGE_)       // 786432
#define OUT_IO       (OUT_ENERGY  + (size_t)B_)             // 786944
#define OUT_NEWMEM   (OUT_IO      + (size_t)B_*IOC_)        // 918016
#define OUT_WEIGHTS  (OUT_NEWMEM  + (size_t)B_*SLOTS_*MEM_) // 68026880

// Scratch layout (floats)
#define S_LAT1    0u
#define S_READY   (S_LAT1   + (size_t)B_*HID_)     // 524288
#define S_QUERY   (S_READY  + (size_t)B_*EDGE_)
#define S_VALUE   (S_QUERY  + (size_t)B_*MEM_)
#define S_READ    (S_VALUE  + (size_t)B_*MEM_)
#define S_GATE    (S_READ   + (size_t)B_*MEM_)
#define S_LOGITS  (S_GATE   + (size_t)B_)
#define S_CAT     (S_LOGITS + (size_t)B_*SLOTS_)
#define S_H1      (S_CAT    + (size_t)B_*CATK_)
#define S_ADAPT   (S_H1     + (size_t)B_*EDGE_)
#define S_FEXP    (S_ADAPT  + (size_t)B_*EDGE_)
#define S_GFR     (S_FEXP   + (size_t)B_*EDGE_)
#define S_EEXP    (S_GFR    + (size_t)B_*EDGE_)
#define S_NUMER   (S_EEXP   + (size_t)IOC_*EDGE_)
#define S_DENOM   (S_NUMER  + (size_t)B_*IOC_)
#define S_TOTAL   (S_DENOM  + (size_t)B_*IOC_)

__device__ float g_scratch[S_TOTAL];

// ---------------------------------------------------------------------------
// Generic tiled SGEMM: C[m,n] = act( add[m,n] + bias[n] + sum_k A[m,k]*B[n,k] )
// A:[M,K] row-major, B:[N,K] row-major (i.e., C = A @ B^T).
// Requires M%64==0, N%64==0, K%16==0 (true for every call here).
// act: 0=none 1=silu 2=sigmoid 3=relu
// ---------------------------------------------------------------------------
#define BM 64
#define BN 64
#define BK 16

__global__ __launch_bounds__(256) void gemm_bias_act(
    const float* __restrict__ A, const float* __restrict__ Bm,
    const float* __restrict__ bias, const float* __restrict__ add,
    float* __restrict__ C, int M, int N, int K, int act)
{
    __shared__ float As[BK][BM];
    __shared__ float Bs[BK][BN];

    const int tid = threadIdx.x;
    const int tx = tid & 15;          // 0..15 -> n
    const int ty = tid >> 4;          // 0..15 -> m
    const int bm = blockIdx.y * BM;
    const int bn = blockIdx.x * BN;

    const int lr = tid >> 2;          // 0..63 row within tile
    const int lc = (tid & 3) << 2;    // 0,4,8,12 k-offset

    float acc[4][4];
#pragma unroll
    for (int i = 0; i < 4; i++)
#pragma unroll
        for (int j = 0; j < 4; j++) acc[i][j] = 0.f;

    for (int k0 = 0; k0 < K; k0 += BK) {
        float4 a4 = *(const float4*)(A + (size_t)(bm + lr) * K + k0 + lc);
        float4 b4 = *(const float4*)(Bm + (size_t)(bn + lr) * K + k0 + lc);
        As[lc + 0][lr] = a4.x; As[lc + 1][lr] = a4.y;
        As[lc + 2][lr] = a4.z; As[lc + 3][lr] = a4.w;
        Bs[lc + 0][lr] = b4.x; Bs[lc + 1][lr] = b4.y;
        Bs[lc + 2][lr] = b4.z; Bs[lc + 3][lr] = b4.w;
        __syncthreads();
#pragma unroll
        for (int k = 0; k < BK; k++) {
            float ar[4], br[4];
#pragma unroll
            for (int i = 0; i < 4; i++) ar[i] = As[k][ty * 4 + i];
#pragma unroll
            for (int j = 0; j < 4; j++) br[j] = Bs[k][tx * 4 + j];
#pragma unroll
            for (int i = 0; i < 4; i++)
#pragma unroll
                for (int j = 0; j < 4; j++) acc[i][j] += ar[i] * br[j];
        }
        __syncthreads();
    }

#pragma unroll
    for (int i = 0; i < 4; i++) {
        const int m = bm + ty * 4 + i;
#pragma unroll
        for (int j = 0; j < 4; j++) {
            const int n = bn + tx * 4 + j;
            float v = acc[i][j];
            if (bias) v += bias[n];
            if (add)  v += add[(size_t)m * N + n];
            if (act == 1)      v = v / (1.f + __expf(-v));       // silu
            else if (act == 2) v = 1.f / (1.f + __expf(-v));     // sigmoid
            else if (act == 3) v = fmaxf(v, 0.f);                // relu
            C[(size_t)m * N + n] = v;
        }
    }
}

// ---------------------------------------------------------------------------
// Small reduction helpers / kernels
// ---------------------------------------------------------------------------
__device__ __forceinline__ float warp_sum(float v) {
#pragma unroll
    for (int o = 16; o; o >>= 1) v += __shfl_xor_sync(0xffffffffu, v, o);
    return v;
}

// energy[b] = relu( dot(latent[b,:HID], w[:HID]) + b0 )
__global__ void energy_k(const float* __restrict__ latent,
                         const float* __restrict__ w,
                         const float* __restrict__ b0,
                         float* __restrict__ out)
{
    __shared__ float sm[8];
    const int b = blockIdx.x;
    float acc = 0.f;
    for (int i = threadIdx.x; i < HID_; i += 256)
        acc += latent[(size_t)b * HID_ + i] * w[i];
    acc = warp_sum(acc);
    if ((threadIdx.x & 31) == 0) sm[threadIdx.x >> 5] = acc;
    __syncthreads();
    if (threadIdx.x == 0) {
        float s = 0.f;
        for (int i = 0; i < 8; i++) s += sm[i];
        out[b] = fmaxf(s + b0[0], 0.f);
    }
}

// gate[b] = sigmoid( dot(latent[b], wg[0:HID]) + dot(read[b], wg[HID:HID+MEM]) + wb )
__global__ void gate_k(const float* __restrict__ latent,
                       const float* __restrict__ readv,
                       const float* __restrict__ wg,
                       const float* __restrict__ wb,
                       float* __restrict__ gate)
{
    __shared__ float sm[8];
    const int b = blockIdx.x;
    float acc = 0.f;
    for (int i = threadIdx.x; i < HID_; i += 256)
        acc += latent[(size_t)b * HID_ + i] * wg[i];
    for (int i = threadIdx.x; i < MEM_; i += 256)
        acc += readv[(size_t)b * MEM_ + i] * wg[HID_ + i];
    acc = warp_sum(acc);
    if ((threadIdx.x & 31) == 0) sm[threadIdx.x >> 5] = acc;
    __syncthreads();
    if (threadIdx.x == 0) {
        float s = 0.f;
        for (int i = 0; i < 8; i++) s += sm[i];
        gate[b] = 1.f / (1.f + __expf(-(s + wb[0])));
    }
}

// Row softmax over 256 logits -> weights (256 threads/block, one block per row)
__global__ void softmax256_k(const float* __restrict__ logits,
                             float* __restrict__ out)
{
    __shared__ float sm[8];
    const int b = blockIdx.x;
    const int t = threadIdx.x;
    float x = logits[(size_t)b * SLOTS_ + t];

    float m = x;
#pragma unroll
    for (int o = 16; o; o >>= 1) m = fmaxf(m, __shfl_xor_sync(0xffffffffu, m, o));
    if ((t & 31) == 0) sm[t >> 5] = m;
    __syncthreads();
    float mx = sm[0];
    for (int i = 1; i < 8; i++) mx = fmaxf(mx, sm[i]);
    __syncthreads();

    float e = __expf(x - mx);
    float s = warp_sum(e);
    if ((t & 31) == 0) sm[t >> 5] = s;
    __syncthreads();
    float tot = 0.f;
    for (int i = 0; i < 8; i++) tot += sm[i];

    out[(size_t)b * SLOTS_ + t] = e / tot;
}

// read[b,d] = sum_s weights[b,s] * memory[b,s,d]   (float4 over d)
__global__ void read_k(const float* __restrict__ w,
                       const float* __restrict__ mem,
                       float* __restrict__ readout)
{
    __shared__ float ws[SLOTS_];
    const int b = blockIdx.x;
    const int t = threadIdx.x;              // 128 threads, d4 = t
    ws[t]       = w[(size_t)b * SLOTS_ + t];
    ws[t + 128] = w[(size_t)b * SLOTS_ + t + 128];
    __syncthreads();

    const float4* m4 = (const float4*)(mem + (size_t)b * SLOTS_ * MEM_);
    float4 acc = make_float4(0.f, 0.f, 0.f, 0.f);
#pragma unroll 4
    for (int s = 0; s < SLOTS_; s++) {
        float4 mm = m4[(size_t)s * (MEM_ / 4) + t];
        float wv = ws[s];
        acc.x += wv * mm.x; acc.y += wv * mm.y;
        acc.z += wv * mm.z; acc.w += wv * mm.w;
    }
    ((float4*)(readout + (size_t)b * MEM_))[t] = acc;
}

// new_memory = memory + gw*(value - memory),  gw = gate[b]*weights[b,s]
__global__ void newmem_k(const float* __restrict__ mem,
                         const float* __restrict__ value,
                         const float* __restrict__ gate,
                         const float* __restrict__ weights,
                         float* __restrict__ nm)
{
    const int i = blockIdx.x * 256 + threadIdx.x;   // float4 index, total 2^24
    const int d4 = i & (MEM_ / 4 - 1);              // 0..127
    const int s  = (i >> 7) & (SLOTS_ - 1);         // 0..255
    const int b  = i >> 15;
    const float gw = gate[b] * weights[(size_t)b * SLOTS_ + s];
    float4 m = ((const float4*)mem)[i];
    float4 v = ((const float4*)value)[(size_t)b * (MEM_ / 4) + d4];
    float4 o;
    o.x = m.x + gw * (v.x - m.x);
    o.y = m.y + gw * (v.y - m.y);
    o.z = m.z + gw * (v.z - m.z);
    o.w = m.w + gw * (v.w - m.w);
    ((float4*)nm)[i] = o;
}

// cat[b, 0:512]=refined, cat[b,512:544]=remap
__global__ void concat_k(const float* __restrict__ refined,
                         const float* __restrict__ remap,
                         float* __restrict__ cat)
{
    const int idx = blockIdx.x * 256 + threadIdx.x;
    if (idx >= B_ * CATK_) return;
    const int b = idx / CATK_;
    const int j = idx - b * CATK_;
    cat[idx] = (j < EDGE_) ? refined[(size_t)b * EDGE_ + j]
                           : remap[(size_t)b * GRP_ + (j - EDGE_)];
}

// E = exp(base_map)
__global__ void expE_k(const float* __restrict__ bm, float* __restrict__ E)
{
    const int i = blockIdx.x * 256 + threadIdx.x;
    if (i < IOC_ * EDGE_) E[i] = __expf(bm[i]);
}

// F = exp(adapt); G = F * refined
__global__ void expFG_k(const float* __restrict__ adapt,
                        const float* __restrict__ refined,
                        float* __restrict__ F, float* __restrict__ G)
{
    const int i = blockIdx.x * 256 + threadIdx.x;
    if (i < B_ * EDGE_) {
        float f = __expf(adapt[i]);
        F[i] = f;
        G[i] = f * refined[i];
    }
}

// io = numer / denom
__global__ void div_k(const float* __restrict__ num,
                      const float* __restrict__ den,
                      float* __restrict__ io)
{
    const int i = blockIdx.x * 256 + threadIdx.x;
    if (i < B_ * IOC_) io[i] = num[i] / den[i];
}

// ---------------------------------------------------------------------------
// Launch
// ---------------------------------------------------------------------------
extern "C" void kernel_launch(void* const* d_in, const int* in_sizes, int n_in,
                              void* d_out, int out_size)
{
    (void)in_sizes; (void)n_in; (void)out_size;

    const float* signal     = (const float*)d_in[0];
    const float* memory     = (const float*)d_in[1];
    const float* remap_code = (const float*)d_in[2];
    const float* enc_w1     = (const float*)d_in[3];
    const float* enc_b1     = (const float*)d_in[4];
    const float* enc_w2     = (const float*)d_in[5];
    const float* enc_b2     = (const float*)d_in[6];
    const float* edge_w     = (const float*)d_in[7];
    const float* edge_b     = (const float*)d_in[8];
    const float* energy_w   = (const float*)d_in[9];
    const float* energy_b   = (const float*)d_in[10];
    const float* rq_w       = (const float*)d_in[11];
    const float* rq_b       = (const float*)d_in[12];
    const float* wg_w       = (const float*)d_in[13];
    const float* wg_b       = (const float*)d_in[14];
    const float* wv_w       = (const float*)d_in[15];
    const float* wv_b       = (const float*)d_in[16];
    const float* memory_key = (const float*)d_in[17];
    const float* m2e_w      = (const float*)d_in[18];
    const float* m2e_b      = (const float*)d_in[19];
    const float* base_map   = (const float*)d_in[20];
    const float* a1_w       = (const float*)d_in[21];
    const float* a1_b       = (const float*)d_in[22];
    const float* a2_w       = (const float*)d_in[23];
    const float* a2_b       = (const float*)d_in[24];

    float* out = (float*)d_out;
    float* o_latent  = out + OUT_LATENT;
    float* o_refined = out + OUT_REFINED;
    float* o_energy  = out + OUT_ENERGY;
    float* o_io      = out + OUT_IO;
    float* o_newmem  = out + OUT_NEWMEM;
    float* o_weights = out + OUT_WEIGHTS;

    float* s = nullptr;
    cudaGetSymbolAddress((void**)&s, g_scratch);
    float* lat1   = s + S_LAT1;
    float* ready  = s + S_READY;
    float* query  = s + S_QUERY;
    float* value  = s + S_VALUE;
    float* readv  = s + S_READ;
    float* gate   = s + S_GATE;
    float* logits = s + S_LOGITS;
    float* cat    = s + S_CAT;
    float* h1     = s + S_H1;
    float* adapt  = s + S_ADAPT;
    float* Fx     = s + S_FEXP;
    float* Gx     = s + S_GFR;
    float* Ex     = s + S_EEXP;
    float* numer  = s + S_NUMER;
    float* denom  = s + S_DENOM;

    dim3 blk(256);
    // 1) lat1 = silu(signal @ enc_w1^T + enc_b1)     [512,1024]
    gemm_bias_act<<<dim3(HID_/BN, B_/BM), blk>>>(signal, enc_w1, enc_b1, nullptr, lat1, B_, HID_, SIG_, 1);
    // 2) latent = silu(lat1 @ enc_w2^T + enc_b2)     -> d_out (latent output)
    gemm_bias_act<<<dim3(HID_/BN, B_/BM), blk>>>(lat1, enc_w2, enc_b2, nullptr, o_latent, B_, HID_, HID_, 1);
    // 3) readiness = sigmoid(latent @ edge_w^T + edge_b)
    gemm_bias_act<<<dim3(EDGE_/BN, B_/BM), blk>>>(o_latent, edge_w, edge_b, nullptr, ready, B_, EDGE_, HID_, 2);
    // 4) query = latent @ rq_w^T + rq_b
    gemm_bias_act<<<dim3(MEM_/BN, B_/BM), blk>>>(o_latent, rq_w, rq_b, nullptr, query, B_, MEM_, HID_, 0);
    // 5) value = latent @ wv_w^T + wv_b
    gemm_bias_act<<<dim3(MEM_/BN, B_/BM), blk>>>(o_latent, wv_w, wv_b, nullptr, value, B_, MEM_, HID_, 0);
    // 6) energy = relu(latent @ energy_w^T + energy_b)
    energy_k<<<B_, 256>>>(o_latent, energy_w, energy_b, o_energy);
    // 7) logits = query @ memory_key^T
    gemm_bias_act<<<dim3(SLOTS_/BN, B_/BM), blk>>>(query, memory_key, nullptr, nullptr, logits, B_, SLOTS_, MEM_, 0);
    // 8) weights = softmax(logits) -> d_out
    softmax256_k<<<B_, 256>>>(logits, o_weights);
    // 9) read[b] = weights[b] @ memory[b]
    read_k<<<B_, 128>>>(o_weights, memory, readv);
    // 10) gate
    gate_k<<<B_, 256>>>(o_latent, readv, wg_w, wg_b, gate);
    // 11) new_memory -> d_out
    newmem_k<<<(B_*SLOTS_*MEM_/4)/256, 256>>>(memory, value, gate, o_weights, o_newmem);
    // 12) refined = sigmoid(readiness + read @ m2e_w^T + m2e_b) -> d_out
    gemm_bias_act<<<dim3(EDGE_/BN, B_/BM), blk>>>(readv, m2e_w, m2e_b, ready, o_refined, B_, EDGE_, MEM_, 2);
    // 13) cat = [refined, remap_code]
    concat_k<<<(B_*CATK_ + 255)/256, 256>>>(o_refined, remap_code, cat);
    // 14) h1 = silu(cat @ a1_w^T + a1_b)
    gemm_bias_act<<<dim3(EDGE_/BN, B_/BM), blk>>>(cat, a1_w, a1_b, nullptr, h1, B_, EDGE_, CATK_, 1);
    // 15) adapt = h1 @ a2_w^T + a2_b
    gemm_bias_act<<<dim3(EDGE_/BN, B_/BM), blk>>>(h1, a2_w, a2_b, nullptr, adapt, B_, EDGE_, EDGE_, 0);
    // 16) E = exp(base_map); F = exp(adapt); G = F*refined
    expE_k<<<(IOC_*EDGE_ + 255)/256, 256>>>(base_map, Ex);
    expFG_k<<<(B_*EDGE_ + 255)/256, 256>>>(adapt, o_refined, Fx, Gx);
    // 17/18) numer = G @ E^T ; denom = F @ E^T
    gemm_bias_act<<<dim3(IOC_/BN, B_/BM), blk>>>(Gx, Ex, nullptr, nullptr, numer, B_, IOC_, EDGE_, 0);
    gemm_bias_act<<<dim3(IOC_/BN, B_/BM), blk>>>(Fx, Ex, nullptr, nullptr, denom, B_, IOC_, EDGE_, 0);
    // 19) io = numer / denom -> d_out
    div_k<<<(B_*IOC_ + 255)/256, 256>>>(numer, denom, o_io);
}

// round 4
// speedup vs baseline: 1.9966x; 1.9966x over previous
#include <cuda_runtime.h>
#include <cuda_bf16.h>
#include <cstdint>
#include <cstddef>

// ---------------------------------------------------------------------------
// Problem dims
// ---------------------------------------------------------------------------
#define B_    512
#define SIG_  512
#define HID_  1024
#define EDGE_ 512
#define SLOTS_ 256
#define MEM_  512
#define IOC_  256
#define GRP_  32
#define CATK_ (EDGE_ + GRP_)   // 544

// Output layout (floats): latent, refined, energy, io, new_memory, weights
#define OUT_LATENT   0u
#define OUT_REFINED  (OUT_LATENT  + (size_t)B_*HID_)
#define OUT_ENERGY   (OUT_REFINED + (size_t)B_*EDGE_)
#define OUT_IO       (OUT_ENERGY  + (size_t)B_)
#define OUT_NEWMEM   (OUT_IO      + (size_t)B_*IOC_)
#define OUT_WEIGHTS  (OUT_NEWMEM  + (size_t)B_*SLOTS_*MEM_)

// Scratch layout (floats)
#define S_LAT1    0u
#define S_READY   (S_LAT1   + (size_t)B_*HID_)
#define S_QUERY   (S_READY  + (size_t)B_*EDGE_)
#define S_VALUE   (S_QUERY  + (size_t)B_*MEM_)
#define S_READ    (S_VALUE  + (size_t)B_*MEM_)
#define S_GATE    (S_READ   + (size_t)B_*MEM_)
#define S_CAT     (S_GATE   + (size_t)B_)
#define S_H1      (S_CAT    + (size_t)B_*CATK_)
#define S_FEXP    (S_H1     + (size_t)B_*EDGE_)
#define S_GFR     (S_FEXP   + (size_t)B_*EDGE_)
#define S_EEXP    (S_GFR    + (size_t)B_*EDGE_)
#define S_PART    (S_EEXP   + (size_t)IOC_*EDGE_)
#define PART_SZ   ((size_t)2*B_*1536)                 // max: gemm3 partials
#define S_TOTAL   (S_PART + PART_SZ)

__device__ float g_scratch[S_TOTAL];

#define ACT_NONE 0
#define ACT_SILU 1
#define ACT_SIG  2

__device__ __forceinline__ float apply_act(float v, int act) {
    if (act == ACT_SILU) return v / (1.f + __expf(-v));
    if (act == ACT_SIG)  return 1.f / (1.f + __expf(-v));
    return v;
}

// ---------------------------------------------------------------------------
// Double-buffered SGEMM core: 64x64 tile, BK=16, 256 threads, 4x4/thread.
// Ap/Bp already offset to (tile_row + lr, lc). nt = number of 16-wide K tiles.
// ---------------------------------------------------------------------------
__device__ __forceinline__ void sgemm_core(
    const float* __restrict__ Ap, const float* __restrict__ Bp,
    int lda, int ldb, int nt, float (&acc)[4][4],
    float (*As)[16][64], float (*Bs)[16][64],
    int lr, int lc, int ty, int tx)
{
    float4 a4 = *(const float4*)(Ap);
    float4 b4 = *(const float4*)(Bp);
    As[0][lc + 0][lr] = a4.x; As[0][lc + 1][lr] = a4.y;
    As[0][lc + 2][lr] = a4.z; As[0][lc + 3][lr] = a4.w;
    Bs[0][lc + 0][lr] = b4.x; Bs[0][lc + 1][lr] = b4.y;
    Bs[0][lc + 2][lr] = b4.z; Bs[0][lc + 3][lr] = b4.w;
    __syncthreads();

    for (int t = 0; t < nt; t++) {
        const int cur = t & 1, nxt = cur ^ 1;
        if (t + 1 < nt) {
            a4 = *(const float4*)(Ap + (t + 1) * 16);
            b4 = *(const float4*)(Bp + (t + 1) * 16);
        }
#pragma unroll
        for (int k = 0; k < 16; k++) {
            float4 av = *(const float4*)&As[cur][k][ty * 4];
            float4 bv = *(const float4*)&Bs[cur][k][tx * 4];
            acc[0][0] += av.x * bv.x; acc[0][1] += av.x * bv.y;
            acc[0][2] += av.x * bv.z; acc[0][3] += av.x * bv.w;
            acc[1][0] += av.y * bv.x; acc[1][1] += av.y * bv.y;
            acc[1][2] += av.y * bv.z; acc[1][3] += av.y * bv.w;
            acc[2][0] += av.z * bv.x; acc[2][1] += av.z * bv.y;
            acc[2][2] += av.z * bv.z; acc[2][3] += av.z * bv.w;
            acc[3][0] += av.w * bv.x; acc[3][1] += av.w * bv.y;
            acc[3][2] += av.w * bv.z; acc[3][3] += av.w * bv.w;
        }
        if (t + 1 < nt) {
            As[nxt][lc + 0][lr] = a4.x; As[nxt][lc + 1][lr] = a4.y;
            As[nxt][lc + 2][lr] = a4.z; As[nxt][lc + 3][lr] = a4.w;
            Bs[nxt][lc + 0][lr] = b4.x; Bs[nxt][lc + 1][lr] = b4.y;
            Bs[nxt][lc + 2][lr] = b4.z; Bs[nxt][lc + 3][lr] = b4.w;
        }
        __syncthreads();
    }
}

// Full GEMM with inline epilogue: C = act(bias + A @ B^T). grid (N/64, M/64).
__global__ __launch_bounds__(256) void k_gemm(
    const float* __restrict__ A, int lda,
    const float* __restrict__ Bm, int ldb,
    const float* __restrict__ bias,
    float* __restrict__ C, int N, int K, int act)
{
    __shared__ float As[2][16][64], Bs[2][16][64];
    const int tid = threadIdx.x;
    const int tx = tid & 15, ty = tid >> 4;
    const int lr = tid >> 2, lc = (tid & 3) << 2;
    const int bm = blockIdx.y * 64, bn = blockIdx.x * 64;

    float acc[4][4] = {};
    sgemm_core(A + (size_t)(bm + lr) * lda + lc,
               Bm + (size_t)(bn + lr) * ldb + lc,
               lda, ldb, K / 16, acc, As, Bs, lr, lc, ty, tx);

#pragma unroll
    for (int i = 0; i < 4; i++) {
        const int m = bm + ty * 4 + i;
#pragma unroll
        for (int j = 0; j < 4; j++) {
            const int n = bn + tx * 4 + j;
            float v = acc[i][j] + (bias ? bias[n] : 0.f);
            C[(size_t)m * N + n] = apply_act(v, act);
        }
    }
}

// Split-K partial GEMM: part[z][m][n] = A[:,z-slice] @ B[:,z-slice]^T.
// grid (N/64, M/64, S). tiles = K-tiles per split. M = gridDim.y*64.
__global__ __launch_bounds__(256) void k_gemm_sk(
    const float* __restrict__ A, int lda,
    const float* __restrict__ Bm, int ldb,
    float* __restrict__ part, int N, int tiles)
{
    __shared__ float As[2][16][64], Bs[2][16][64];
    const int tid = threadIdx.x;
    const int tx = tid & 15, ty = tid >> 4;
    const int lr = tid >> 2, lc = (tid & 3) << 2;
    const int bm = blockIdx.y * 64, bn = blockIdx.x * 64;
    const int k0 = blockIdx.z * tiles * 16;
    const int M = gridDim.y * 64;

    float acc[4][4] = {};
    sgemm_core(A + (size_t)(bm + lr) * lda + k0 + lc,
               Bm + (size_t)(bn + lr) * ldb + k0 + lc,
               lda, ldb, tiles, acc, As, Bs, lr, lc, ty, tx);

    float* p = part + (size_t)blockIdx.z * M * N;
#pragma unroll
    for (int i = 0; i < 4; i++) {
        const int m = bm + ty * 4 + i;
#pragma unroll
        for (int j = 0; j < 4; j++)
            p[(size_t)m * N + bn + tx * 4 + j] = acc[i][j];
    }
}

// Fused edge|rq|wv split-K GEMM. A = latent [512,1024]. grid (24, 8, 2).
// Partial layout: part[z][m][n_total], n_total in [0,1536).
__global__ __launch_bounds__(256) void k_gemm3_sk(
    const float* __restrict__ A,
    const float* __restrict__ B0, const float* __restrict__ B1,
    const float* __restrict__ B2,
    float* __restrict__ part, int tiles)
{
    __shared__ float As[2][16][64], Bs[2][16][64];
    const int tid = threadIdx.x;
    const int tx = tid & 15, ty = tid >> 4;
    const int lr = tid >> 2, lc = (tid & 3) << 2;
    const int bm = blockIdx.y * 64;
    const int g = blockIdx.x >> 3;           // which weight matrix
    const int bn_loc = (blockIdx.x & 7) * 64;
    const int k0 = blockIdx.z * tiles * 16;
    const float* Bsel = (g == 0) ? B0 : (g == 1) ? B1 : B2;

    float acc[4][4] = {};
    sgemm_core(A + (size_t)(bm + lr) * HID_ + k0 + lc,
               Bsel + (size_t)(bn_loc + lr) * HID_ + k0 + lc,
               HID_, HID_, tiles, acc, As, Bs, lr, lc, ty, tx);

    float* p = part + (size_t)blockIdx.z * B_ * 1536;
    const int bn = blockIdx.x * 64;
#pragma unroll
    for (int i = 0; i < 4; i++) {
        const int m = bm + ty * 4 + i;
#pragma unroll
        for (int j = 0; j < 4; j++)
            p[(size_t)m * 1536 + bn + tx * 4 + j] = acc[i][j];
    }
}

// Fused numer|denom split-K GEMM vs E. grid (8, 8, 2): x<4 -> numer(A=G), else denom(A=F)
// part layout: [(sel*2+z)][m][n], n in [0,256)
__global__ __launch_bounds__(256) void k_ndpair_sk(
    const float* __restrict__ G, const float* __restrict__ F,
    const float* __restrict__ E,
    float* __restrict__ part, int tiles)
{
    __shared__ float As[2][16][64], Bs[2][16][64];
    const int tid = threadIdx.x;
    const int tx = tid & 15, ty = tid >> 4;
    const int lr = tid >> 2, lc = (tid & 3) << 2;
    const int bm = blockIdx.y * 64;
    const int sel = blockIdx.x >> 2;
    const int bn = (blockIdx.x & 3) * 64;
    const int k0 = blockIdx.z * tiles * 16;
    const float* A = sel ? F : G;

    float acc[4][4] = {};
    sgemm_core(A + (size_t)(bm + lr) * EDGE_ + k0 + lc,
               E + (size_t)(bn + lr) * EDGE_ + k0 + lc,
               EDGE_, EDGE_, tiles, acc, As, Bs, lr, lc, ty, tx);

    float* p = part + (size_t)(sel * 2 + blockIdx.z) * B_ * IOC_;
#pragma unroll
    for (int i = 0; i < 4; i++) {
        const int m = bm + ty * 4 + i;
#pragma unroll
        for (int j = 0; j < 4; j++)
            p[(size_t)m * IOC_ + bn + tx * 4 + j] = acc[i][j];
    }
}

// ---------------------------------------------------------------------------
// Combine / epilogue kernels
// ---------------------------------------------------------------------------

// gemm3 combine: readiness=sigmoid(.+eb), query=.+rb, value=.+vb
__global__ void k_comb3(const float* __restrict__ part,
                        const float* __restrict__ eb, const float* __restrict__ rb,
                        const float* __restrict__ vb,
                        float* __restrict__ ready, float* __restrict__ query,
                        float* __restrict__ value)
{
    const size_t i = (size_t)blockIdx.x * 256 + threadIdx.x;   // < 512*1536
    const int m = (int)(i / 1536), n = (int)(i % 1536);
    float v = part[i] + part[i + (size_t)B_ * 1536];
    if (n < 512)       ready[(size_t)m * 512 + n] = 1.f / (1.f + __expf(-(v + eb[n])));
    else if (n < 1024) query[(size_t)m * 512 + (n - 512)] = v + rb[n - 512];
    else               value[(size_t)m * 512 + (n - 1024)] = v + vb[n - 1024];
}

// generic 2-way combine: C = act(p0+p1 + bias[n] + add[i])
__global__ void k_comb2(const float* __restrict__ part,
                        const float* __restrict__ bias,
                        const float* __restrict__ add,
                        float* __restrict__ C, size_t total, int act)
{
    const size_t i = (size_t)blockIdx.x * 256 + threadIdx.x;
    if (i >= total) return;
    const int n = (int)(i & (EDGE_ - 1));
    float v = part[i] + part[i + total] + bias[n];
    if (add) v += add[i];
    C[i] = apply_act(v, act);
}

// a2 combine -> F = exp(adapt), G = F * refined
__global__ void k_comb_expFG(const float* __restrict__ part,
                             const float* __restrict__ bias,
                             const float* __restrict__ refined,
                             float* __restrict__ F, float* __restrict__ G)
{
    const size_t i = (size_t)blockIdx.x * 256 + threadIdx.x;   // < 512*512
    const int n = (int)(i & (EDGE_ - 1));
    const size_t total = (size_t)B_ * EDGE_;
    float f = __expf(part[i] + part[i + total] + bias[n]);
    F[i] = f;
    G[i] = f * refined[i];
}

// io = (n0+n1)/(d0+d1)
__global__ void k_comb_io(const float* __restrict__ part, float* __restrict__ io)
{
    const size_t i = (size_t)blockIdx.x * 256 + threadIdx.x;   // < 512*256
    const size_t T = (size_t)B_ * IOC_;
    float num = part[i] + part[i + T];
    float den = part[i + 2 * T] + part[i + 3 * T];
    io[i] = num / den;
}

// softmax over 256 logits assembled from 4 K-split partials
__global__ void k_softmax4(const float* __restrict__ part, float* __restrict__ out)
{
    __shared__ float sm[8];
    const int b = blockIdx.x, t = threadIdx.x;
    const size_t T = (size_t)B_ * SLOTS_;
    float x = part[(size_t)b * SLOTS_ + t] + part[(size_t)b * SLOTS_ + t + T]
            + part[(size_t)b * SLOTS_ + t + 2 * T] + part[(size_t)b * SLOTS_ + t + 3 * T];

    float m = x;
#pragma unroll
    for (int o = 16; o; o >>= 1) m = fmaxf(m, __shfl_xor_sync(0xffffffffu, m, o));
    if ((t & 31) == 0) sm[t >> 5] = m;
    __syncthreads();
    float mx = sm[0];
    for (int i = 1; i < 8; i++) mx = fmaxf(mx, sm[i]);
    __syncthreads();

    float e = __expf(x - mx);
    float s = e;
#pragma unroll
    for (int o = 16; o; o >>= 1) s += __shfl_xor_sync(0xffffffffu, s, o);
    if ((t & 31) == 0) sm[t >> 5] = s;
    __syncthreads();
    float tot = 0.f;
    for (int i = 0; i < 8; i++) tot += sm[i];

    out[(size_t)b * SLOTS_ + t] = e / tot;
}

// ---------------------------------------------------------------------------
// Misc small kernels
// ---------------------------------------------------------------------------
__device__ __forceinline__ float warp_sum(float v) {
#pragma unroll
    for (int o = 16; o; o >>= 1) v += __shfl_xor_sync(0xffffffffu, v, o);
    return v;
}

__global__ void energy_k(const float* __restrict__ latent,
                         const float* __restrict__ w,
                         const float* __restrict__ b0,
                         float* __restrict__ out)
{
    __shared__ float sm[8];
    const int b = blockIdx.x;
    float acc = 0.f;
    for (int i = threadIdx.x; i < HID_; i += 256)
        acc += latent[(size_t)b * HID_ + i] * w[i];
    acc = warp_sum(acc);
    if ((threadIdx.x & 31) == 0) sm[threadIdx.x >> 5] = acc;
    __syncthreads();
    if (threadIdx.x == 0) {
        float s = 0.f;
        for (int i = 0; i < 8; i++) s += sm[i];
        out[b] = fmaxf(s + b0[0], 0.f);
    }
}

__global__ void gate_k(const float* __restrict__ latent,
                       const float* __restrict__ readv,
                       const float* __restrict__ wg,
                       const float* __restrict__ wb,
                       float* __restrict__ gate)
{
    __shared__ float sm[8];
    const int b = blockIdx.x;
    float acc = 0.f;
    for (int i = threadIdx.x; i < HID_; i += 256)
        acc += latent[(size_t)b * HID_ + i] * wg[i];
    for (int i = threadIdx.x; i < MEM_; i += 256)
        acc += readv[(size_t)b * MEM_ + i] * wg[HID_ + i];
    acc = warp_sum(acc);
    if ((threadIdx.x & 31) == 0) sm[threadIdx.x >> 5] = acc;
    __syncthreads();
    if (threadIdx.x == 0) {
        float s = 0.f;
        for (int i = 0; i < 8; i++) s += sm[i];
        gate[b] = 1.f / (1.f + __expf(-(s + wb[0])));
    }
}

__global__ void read_k(const float* __restrict__ w,
                       const float* __restrict__ mem,
                       float* __restrict__ readout)
{
    __shared__ float ws[SLOTS_];
    const int b = blockIdx.x;
    const int t = threadIdx.x;              // 128 threads
    ws[t]       = w[(size_t)b * SLOTS_ + t];
    ws[t + 128] = w[(size_t)b * SLOTS_ + t + 128];
    __syncthreads();

    const float4* m4 = (const float4*)(mem + (size_t)b * SLOTS_ * MEM_);
    float4 acc = make_float4(0.f, 0.f, 0.f, 0.f);
#pragma unroll 4
    for (int s = 0; s < SLOTS_; s++) {
        float4 mm = m4[(size_t)s * (MEM_ / 4) + t];
        float wv = ws[s];
        acc.x += wv * mm.x; acc.y += wv * mm.y;
        acc.z += wv * mm.z; acc.w += wv * mm.w;
    }
    ((float4*)(readout + (size_t)b * MEM_))[t] = acc;
}

__global__ void newmem_k(const float* __restrict__ mem,
                         const float* __restrict__ value,
                         const float* __restrict__ gate,
                         const float* __restrict__ weights,
                         float* __restrict__ nm)
{
    const int i = blockIdx.x * 256 + threadIdx.x;
    const int d4 = i & (MEM_ / 4 - 1);
    const int s  = (i >> 7) & (SLOTS_ - 1);
    const int b  = i >> 15;
    const float gw = gate[b] * weights[(size_t)b * SLOTS_ + s];
    float4 m = ((const float4*)mem)[i];
    float4 v = ((const float4*)value)[(size_t)b * (MEM_ / 4) + d4];
    float4 o;
    o.x = m.x + gw * (v.x - m.x);
    o.y = m.y + gw * (v.y - m.y);
    o.z = m.z + gw * (v.z - m.z);
    o.w = m.w + gw * (v.w - m.w);
    ((float4*)nm)[i] = o;
}

__global__ void concat_k(const float* __restrict__ refined,
                         const float* __restrict__ remap,
                         float* __restrict__ cat)
{
    const int idx = blockIdx.x * 256 + threadIdx.x;
    if (idx >= B_ * CATK_) return;
    const int b = idx / CATK_;
    const int j = idx - b * CATK_;
    cat[idx] = (j < EDGE_) ? refined[(size_t)b * EDGE_ + j]
                           : remap[(size_t)b * GRP_ + (j - EDGE_)];
}

__global__ void expE_k(const float* __restrict__ bm, float* __restrict__ E)
{
    const int i = blockIdx.x * 256 + threadIdx.x;
    if (i < IOC_ * EDGE_) E[i] = __expf(bm[i]);
}

// ---------------------------------------------------------------------------
// Launch
// ---------------------------------------------------------------------------
extern "C" void kernel_launch(void* const* d_in, const int* in_sizes, int n_in,
                              void* d_out, int out_size)
{
    (void)in_sizes; (void)n_in; (void)out_size;

    const float* signal     = (const float*)d_in[0];
    const float* memory     = (const float*)d_in[1];
    const float* remap_code = (const float*)d_in[2];
    const float* enc_w1     = (const float*)d_in[3];
    const float* enc_b1     = (const float*)d_in[4];
    const float* enc_w2     = (const float*)d_in[5];
    const float* enc_b2     = (const float*)d_in[6];
    const float* edge_w     = (const float*)d_in[7];
    const float* edge_b     = (const float*)d_in[8];
    const float* energy_w   = (const float*)d_in[9];
    const float* energy_b   = (const float*)d_in[10];
    const float* rq_w       = (const float*)d_in[11];
    const float* rq_b       = (const float*)d_in[12];
    const float* wg_w       = (const float*)d_in[13];
    const float* wg_b       = (const float*)d_in[14];
    const float* wv_w       = (const float*)d_in[15];
    const float* wv_b       = (const float*)d_in[16];
    const float* memory_key = (const float*)d_in[17];
    const float* m2e_w      = (const float*)d_in[18];
    const float* m2e_b      = (const float*)d_in[19];
    const float* base_map   = (const float*)d_in[20];
    const float* a1_w       = (const float*)d_in[21];
    const float* a1_b       = (const float*)d_in[22];
    const float* a2_w       = (const float*)d_in[23];
    const float* a2_b       = (const float*)d_in[24];

    float* out = (float*)d_out;
    float* o_latent  = out + OUT_LATENT;
    float* o_refined = out + OUT_REFINED;
    float* o_energy  = out + OUT_ENERGY;
    float* o_io      = out + OUT_IO;
    float* o_newmem  = out + OUT_NEWMEM;
    float* o_weights = out + OUT_WEIGHTS;

    float* s = nullptr;
    cudaGetSymbolAddress((void**)&s, g_scratch);
    float* lat1   = s + S_LAT1;
    float* ready  = s + S_READY;
    float* query  = s + S_QUERY;
    float* value  = s + S_VALUE;
    float* readv  = s + S_READ;
    float* gate   = s + S_GATE;
    float* cat    = s + S_CAT;
    float* h1     = s + S_H1;
    float* Fx     = s + S_FEXP;
    float* Gx     = s + S_GFR;
    float* Ex     = s + S_EEXP;
    float* part   = s + S_PART;

    // independent: E = exp(base_map)
    expE_k<<<(IOC_*EDGE_)/256, 256>>>(base_map, Ex);

    // 1) lat1 = silu(signal @ enc_w1^T + b)          grid 128
    k_gemm<<<dim3(HID_/64, B_/64), 256>>>(signal, SIG_, enc_w1, SIG_, enc_b1,
                                          lat1, HID_, SIG_, ACT_SILU);
    // 2) latent = silu(lat1 @ enc_w2^T + b)          grid 128
    k_gemm<<<dim3(HID_/64, B_/64), 256>>>(lat1, HID_, enc_w2, HID_, enc_b2,
                                          o_latent, HID_, HID_, ACT_SILU);
    // 3) edge|rq|wv fused, split-K=2                 grid 384
    k_gemm3_sk<<<dim3(24, B_/64, 2), 256>>>(o_latent, edge_w, rq_w, wv_w, part, 32);
    k_comb3<<<(B_*1536)/256, 256>>>(part, edge_b, rq_b, wv_b, ready, query, value);
    // 4) energy
    energy_k<<<B_, 256>>>(o_latent, energy_w, energy_b, o_energy);
    // 5) logits split-K=4                            grid 128
    k_gemm_sk<<<dim3(SLOTS_/64, B_/64, 4), 256>>>(query, MEM_, memory_key, MEM_,
                                                  part, SLOTS_, 8);
    // 6) weights = softmax(sum of partials)
    k_softmax4<<<B_, 256>>>(part, o_weights);
    // 7) read
    read_k<<<B_, 128>>>(o_weights, memory, readv);
    // 8) gate
    gate_k<<<B_, 256>>>(o_latent, readv, wg_w, wg_b, gate);
    // 9) new_memory
    newmem_k<<<(B_*SLOTS_*MEM_/4)/256, 256>>>(memory, value, gate, o_weights, o_newmem);
    // 10) m2e split-K=2                              grid 128
    k_gemm_sk<<<dim3(EDGE_/64, B_/64, 2), 256>>>(readv, MEM_, m2e_w, MEM_,
                                                 part, EDGE_, 16);
    k_comb2<<<(B_*EDGE_)/256, 256>>>(part, m2e_b, ready, o_refined,
                                     (size_t)B_*EDGE_, ACT_SIG);
    // 11) cat = [refined, remap]
    concat_k<<<(B_*CATK_ + 255)/256, 256>>>(o_refined, remap_code, cat);
    // 12) a1 split-K=2 (K=544 -> 17 tiles each)      grid 128
    k_gemm_sk<<<dim3(EDGE_/64, B_/64, 2), 256>>>(cat, CATK_, a1_w, CATK_,
                                                 part, EDGE_, 17);
    k_comb2<<<(B_*EDGE_)/256, 256>>>(part, a1_b, nullptr, h1,
                                     (size_t)B_*EDGE_, ACT_SILU);
    // 13) a2 split-K=2 -> F = exp(adapt), G = F*refined
    k_gemm_sk<<<dim3(EDGE_/64, B_/64, 2), 256>>>(h1, EDGE_, a2_w, EDGE_,
                                                 part, EDGE_, 16);
    k_comb_expFG<<<(B_*EDGE_)/256, 256>>>(part, a2_b, o_refined, Fx, Gx);
    // 14) numer|denom pair split-K=2                 grid 128
    k_ndpair_sk<<<dim3(8, B_/64, 2), 256>>>(Gx, Fx, Ex, part, 16);
    // 15) io
    k_comb_io<<<(B_*IOC_)/256, 256>>>(part, o_io);
}